// round 1
// baseline (speedup 1.0000x reference)
#include <cuda_runtime.h>
#include <cuda_bf16.h>
#include <math.h>

#define N_IN   12288
#define H0     256
#define BATCH  8192
#define ROWS_PER_BLOCK 8

// Scratch (static device allocations are allowed)
__device__ float g_ft_wt[N_IN * H0];     // (12288, 256) transposed feature weights
__device__ float g_l1wt[512 * 32];       // (512, 32) transposed
__device__ float g_l2wt[32 * 32];        // (32, 32) transposed
__device__ int   g_side_mode;            // 0=uint8, 1=int32, 2=float32

// ---------------------------------------------------------------------------
// Detect the storage dtype of the boolean 'side' array by byte patterns.
// Reads only the first 8192 bytes, which is safe for uint8 (exactly 8192B),
// int32 (32KB alloc), and float32 (32KB alloc).
//   float32 1.0f = 00 00 80 3F  -> bytes at off%4==3 equal 0x3F
//   uint8   1    -> nonzero bytes at odd offsets
//   int32   1    -> nonzero only at off%4==0
// ---------------------------------------------------------------------------
__global__ void side_mode_kernel(const unsigned char* __restrict__ p) {
    __shared__ int c3F, cOdd;
    if (threadIdx.x == 0) { c3F = 0; cOdd = 0; }
    __syncthreads();
    int l3f = 0, lodd = 0;
    for (int i = threadIdx.x; i < 8192; i += blockDim.x) {
        unsigned char b = p[i];
        if ((i & 3) == 3 && b == 0x3F) l3f++;
        if ((i & 3) != 0 && b != 0)    lodd++;
    }
    atomicAdd(&c3F, l3f);
    atomicAdd(&cOdd, lodd);
    __syncthreads();
    if (threadIdx.x == 0)
        g_side_mode = (c3F > 0) ? 2 : ((cOdd > 0) ? 0 : 1);
}

// ---------------------------------------------------------------------------
// Tiled transpose ft_w (256, 12288) -> g_ft_wt (12288, 256)
// grid (384, 8), block (32, 32)
// ---------------------------------------------------------------------------
__global__ void transpose_ft_kernel(const float* __restrict__ ft_w) {
    __shared__ float tile[32][33];
    int f = blockIdx.x * 32 + threadIdx.x;   // col in input (N_IN)
    int h = blockIdx.y * 32 + threadIdx.y;   // row in input (H0)
    tile[threadIdx.y][threadIdx.x] = ft_w[h * N_IN + f];
    __syncthreads();
    int oh = blockIdx.y * 32 + threadIdx.x;  // col in output (H0)
    int of = blockIdx.x * 32 + threadIdx.y;  // row in output (N_IN)
    g_ft_wt[of * H0 + oh] = tile[threadIdx.x][threadIdx.y];
}

// Transpose the small tail weights.
__global__ void prep_small_kernel(const float* __restrict__ l1w,
                                  const float* __restrict__ l2w) {
    for (int i = threadIdx.x; i < 32 * 512; i += blockDim.x) {
        int r = i / 512, c = i % 512;
        g_l1wt[c * 32 + r] = l1w[i];
    }
    for (int i = threadIdx.x; i < 32 * 32; i += blockDim.x) {
        int r = i / 32, c = i % 32;
        g_l2wt[c * 32 + r] = l2w[i];
    }
}

// ---------------------------------------------------------------------------
// Main kernel: one warp per batch row.
// ---------------------------------------------------------------------------
__device__ __forceinline__ void accum_mask(unsigned mask, int fbase, int lane,
                                           float acc[8]) {
    while (mask) {
        int b = __ffs(mask) - 1;
        mask &= mask - 1;
        int f = fbase + b * 4;
        const float4* wp = (const float4*)(g_ft_wt + (size_t)f * H0);
        float4 a = wp[lane];
        float4 c = wp[32 + lane];
        acc[0] += a.x; acc[1] += a.y; acc[2] += a.z; acc[3] += a.w;
        acc[4] += c.x; acc[5] += c.y; acc[6] += c.z; acc[7] += c.w;
    }
}

__device__ __forceinline__ void scan_side(const float* __restrict__ feat,
                                          int r, int lane, float acc[8]) {
    const float4* rp = (const float4*)(feat + (size_t)r * N_IN);
    for (int base = 0; base < N_IN; base += 512) {
        int q = base >> 2;  // float4 index
        float4 v0 = rp[q + 0 * 32 + lane];
        float4 v1 = rp[q + 1 * 32 + lane];
        float4 v2 = rp[q + 2 * 32 + lane];
        float4 v3 = rp[q + 3 * 32 + lane];
        float4 vs[4] = {v0, v1, v2, v3};
        #pragma unroll
        for (int c = 0; c < 4; c++) {
            int cb = base + c * 128;
            float4 v = vs[c];
            unsigned mx = __ballot_sync(0xffffffffu, v.x != 0.0f);
            unsigned my = __ballot_sync(0xffffffffu, v.y != 0.0f);
            unsigned mz = __ballot_sync(0xffffffffu, v.z != 0.0f);
            unsigned mw = __ballot_sync(0xffffffffu, v.w != 0.0f);
            accum_mask(mx, cb + 0, lane, acc);
            accum_mask(my, cb + 1, lane, acc);
            accum_mask(mz, cb + 2, lane, acc);
            accum_mask(mw, cb + 3, lane, acc);
        }
    }
}

__global__ __launch_bounds__(256, 2) void nnue_main_kernel(
    const float* __restrict__ white, const float* __restrict__ black,
    const void* __restrict__ side,
    const float* __restrict__ ft_b, const float* __restrict__ l1_b,
    const float* __restrict__ l2_b, const float* __restrict__ l3_w,
    const float* __restrict__ l3_b, float* __restrict__ out)
{
    extern __shared__ float sm[];
    float* l1wt_sh = sm;               // 16384 floats
    float* l2wt_sh = sm + 16384;       // 1024 floats
    float* o0_sh   = sm + 17408;       // 8 * 512 floats

    int tid = threadIdx.x;
    for (int i = tid; i < 16384; i += 256) l1wt_sh[i] = g_l1wt[i];
    for (int i = tid; i < 1024;  i += 256) l2wt_sh[i] = g_l2wt[i];
    __syncthreads();

    int lane = tid & 31;
    int wrp  = tid >> 5;
    int r = blockIdx.x * ROWS_PER_BLOCK + wrp;

    // Accumulators init with ft bias.
    // Mapping: acc[j]   <-> h = lane*4 + j       (j = 0..3)
    //          acc[4+j] <-> h = 128 + lane*4 + j (j = 0..3)
    float4 fb0 = ((const float4*)ft_b)[lane];
    float4 fb1 = ((const float4*)ft_b)[32 + lane];
    float aw[8] = {fb0.x, fb0.y, fb0.z, fb0.w, fb1.x, fb1.y, fb1.z, fb1.w};
    float ab[8] = {fb0.x, fb0.y, fb0.z, fb0.w, fb1.x, fb1.y, fb1.z, fb1.w};

    scan_side(white, r, lane, aw);
    scan_side(black, r, lane, ab);

    // side flag (auto-detected dtype)
    int mode = g_side_mode;
    bool s;
    if (mode == 0)      s = ((const unsigned char*)side)[r] != 0;
    else if (mode == 1) s = ((const int*)side)[r] != 0;
    else                s = ((const float*)side)[r] != 0.0f;

    // Build clipped o0 (512) in shared: [us, them] with us = s ? white : black
    float* o = o0_sh + wrp * 512;
    #pragma unroll
    for (int j = 0; j < 4; j++) {
        float w1 = s ? aw[j]     : ab[j];
        float w2 = s ? aw[4 + j] : ab[4 + j];
        float b1 = s ? ab[j]     : aw[j];
        float b2 = s ? ab[4 + j] : aw[4 + j];
        o[lane * 4 + j]       = fminf(fmaxf(w1, 0.0f), 1.0f);
        o[128 + lane * 4 + j] = fminf(fmaxf(w2, 0.0f), 1.0f);
        o[256 + lane * 4 + j] = fminf(fmaxf(b1, 0.0f), 1.0f);
        o[384 + lane * 4 + j] = fminf(fmaxf(b2, 0.0f), 1.0f);
    }
    __syncwarp();

    // L1: o1[lane] = clip(b + sum_i o[i] * l1wt[i*32+lane])
    float s1 = l1_b[lane];
    #pragma unroll 8
    for (int i = 0; i < 512; i++) {
        s1 += o[i] * l1wt_sh[i * 32 + lane];
    }
    float o1 = fminf(fmaxf(s1, 0.0f), 1.0f);

    // L2: o2[lane] = clip(b + sum_i o1[i] * l2wt[i*32+lane])
    float s2 = l2_b[lane];
    #pragma unroll
    for (int i = 0; i < 32; i++) {
        float v = __shfl_sync(0xffffffffu, o1, i);
        s2 += v * l2wt_sh[i * 32 + lane];
    }
    float o2 = fminf(fmaxf(s2, 0.0f), 1.0f);

    // L3 + sigmoid
    float p = o2 * l3_w[lane];
    #pragma unroll
    for (int off = 16; off; off >>= 1)
        p += __shfl_xor_sync(0xffffffffu, p, off);
    if (lane == 0) {
        float t = (p + l3_b[0]) * 1.5f;   // * OUTPUT_SCALE / WDL_SCALE
        out[r] = 1.0f / (1.0f + expf(-t));
    }
}

// ---------------------------------------------------------------------------
extern "C" void kernel_launch(void* const* d_in, const int* in_sizes, int n_in,
                              void* d_out, int out_size) {
    const float* white = (const float*)d_in[0];
    const float* black = (const float*)d_in[1];
    const void*  side  = d_in[2];
    const float* ft_w  = (const float*)d_in[3];
    const float* ft_b  = (const float*)d_in[4];
    const float* l1_w  = (const float*)d_in[5];
    const float* l1_b  = (const float*)d_in[6];
    const float* l2_w  = (const float*)d_in[7];
    const float* l2_b  = (const float*)d_in[8];
    const float* l3_w  = (const float*)d_in[9];
    const float* l3_b  = (const float*)d_in[10];
    float* out = (float*)d_out;

    const int smem_bytes = (16384 + 1024 + ROWS_PER_BLOCK * 512) * 4;  // 86016
    cudaFuncSetAttribute(nnue_main_kernel,
                         cudaFuncAttributeMaxDynamicSharedMemorySize,
                         smem_bytes);

    side_mode_kernel<<<1, 256>>>((const unsigned char*)side);
    transpose_ft_kernel<<<dim3(N_IN / 32, H0 / 32), dim3(32, 32)>>>(ft_w);
    prep_small_kernel<<<1, 256>>>(l1_w, l2_w);
    nnue_main_kernel<<<BATCH / ROWS_PER_BLOCK, 256, smem_bytes>>>(
        white, black, side, ft_b, l1_b, l2_b, l3_w, l3_b, out);
}

// round 2
// speedup vs baseline: 1.5537x; 1.5537x over previous
#include <cuda_runtime.h>
#include <cuda_bf16.h>
#include <math.h>

#define N_IN   12288
#define H0     256
#define BATCH  8192
#define ROWS_PER_BLOCK 8

// Scratch (static device allocations are allowed)
__device__ float g_ft_wt[N_IN * H0];      // (12288, 256) transposed feature weights
__device__ float g_l1wt[512 * 32];        // (512, 32) transposed
__device__ float g_l2wt[32 * 32];         // (32, 32) transposed
__device__ float g_o0[BATCH * 512];       // clipped, side-swapped accumulator
__device__ int   g_side_mode;             // 0=uint8, 1=int32, 2=float32

// ---------------------------------------------------------------------------
// Detect storage dtype of boolean 'side' by byte patterns (first 8192 bytes).
// ---------------------------------------------------------------------------
__global__ void side_mode_kernel(const unsigned char* __restrict__ p) {
    __shared__ int c3F, cOdd;
    if (threadIdx.x == 0) { c3F = 0; cOdd = 0; }
    __syncthreads();
    int l3f = 0, lodd = 0;
    for (int i = threadIdx.x; i < 8192; i += blockDim.x) {
        unsigned char b = p[i];
        if ((i & 3) == 3 && b == 0x3F) l3f++;
        if ((i & 3) != 0 && b != 0)    lodd++;
    }
    atomicAdd(&c3F, l3f);
    atomicAdd(&cOdd, lodd);
    __syncthreads();
    if (threadIdx.x == 0)
        g_side_mode = (c3F > 0) ? 2 : ((cOdd > 0) ? 0 : 1);
}

// ---------------------------------------------------------------------------
// Tiled transpose ft_w (256, 12288) -> g_ft_wt (12288, 256)
// ---------------------------------------------------------------------------
__global__ void transpose_ft_kernel(const float* __restrict__ ft_w) {
    __shared__ float tile[32][33];
    int f = blockIdx.x * 32 + threadIdx.x;
    int h = blockIdx.y * 32 + threadIdx.y;
    tile[threadIdx.y][threadIdx.x] = ft_w[h * N_IN + f];
    __syncthreads();
    int oh = blockIdx.y * 32 + threadIdx.x;
    int of = blockIdx.x * 32 + threadIdx.y;
    g_ft_wt[of * H0 + oh] = tile[threadIdx.x][threadIdx.y];
}

__global__ void prep_small_kernel(const float* __restrict__ l1w,
                                  const float* __restrict__ l2w) {
    for (int i = threadIdx.x; i < 32 * 512; i += blockDim.x) {
        int r = i / 512, c = i % 512;
        g_l1wt[c * 32 + r] = l1w[i];
    }
    for (int i = threadIdx.x; i < 32 * 32; i += blockDim.x) {
        int r = i / 32, c = i % 32;
        g_l2wt[c * 32 + r] = l2w[i];
    }
}

// ---------------------------------------------------------------------------
// Sparse gather-accumulate for the active features in one ballot mask.
// ---------------------------------------------------------------------------
__device__ __forceinline__ void accum_mask(unsigned mask, int fbase, int lane,
                                           float acc[8]) {
    while (mask) {
        int b = __ffs(mask) - 1;
        mask &= mask - 1;
        int f = fbase + b * 4;
        const float4* wp = (const float4*)(g_ft_wt + (size_t)f * H0);
        float4 a = __ldg(wp + lane);
        float4 c = __ldg(wp + 32 + lane);
        acc[0] += a.x; acc[1] += a.y; acc[2] += a.z; acc[3] += a.w;
        acc[4] += c.x; acc[5] += c.y; acc[6] += c.z; acc[7] += c.w;
    }
}

__device__ __forceinline__ void process_chunk(const float4 v[4], int base,
                                              int lane, float acc[8]) {
    #pragma unroll
    for (int c = 0; c < 4; c++) {
        int cb = base + c * 128;
        unsigned mx = __ballot_sync(0xffffffffu, v[c].x != 0.0f);
        unsigned my = __ballot_sync(0xffffffffu, v[c].y != 0.0f);
        unsigned mz = __ballot_sync(0xffffffffu, v[c].z != 0.0f);
        unsigned mw = __ballot_sync(0xffffffffu, v[c].w != 0.0f);
        accum_mask(mx, cb + 0, lane, acc);
        accum_mask(my, cb + 1, lane, acc);
        accum_mask(mz, cb + 2, lane, acc);
        accum_mask(mw, cb + 3, lane, acc);
    }
}

// ---------------------------------------------------------------------------
// Scan kernel: one warp per batch row, no shared memory.
// Interleaves white/black loads (8 LDG.128 in flight), streaming hints.
// ---------------------------------------------------------------------------
__global__ __launch_bounds__(256, 4) void nnue_scan_kernel(
    const float* __restrict__ white, const float* __restrict__ black,
    const void* __restrict__ side, const float* __restrict__ ft_b)
{
    int tid  = threadIdx.x;
    int lane = tid & 31;
    int wrp  = tid >> 5;
    int r = blockIdx.x * ROWS_PER_BLOCK + wrp;

    float4 fb0 = __ldg((const float4*)ft_b + lane);
    float4 fb1 = __ldg((const float4*)ft_b + 32 + lane);
    float aw[8] = {fb0.x, fb0.y, fb0.z, fb0.w, fb1.x, fb1.y, fb1.z, fb1.w};
    float ab[8] = {fb0.x, fb0.y, fb0.z, fb0.w, fb1.x, fb1.y, fb1.z, fb1.w};

    const float4* wrow = (const float4*)(white + (size_t)r * N_IN);
    const float4* brow = (const float4*)(black + (size_t)r * N_IN);

    for (int base = 0; base < N_IN; base += 512) {
        int q = (base >> 2) + lane;
        float4 wv[4], bv[4];
        #pragma unroll
        for (int c = 0; c < 4; c++) wv[c] = __ldcs(wrow + q + c * 32);
        #pragma unroll
        for (int c = 0; c < 4; c++) bv[c] = __ldcs(brow + q + c * 32);
        process_chunk(wv, base, lane, aw);
        process_chunk(bv, base, lane, ab);
    }

    // side flag (auto-detected dtype)
    int mode = g_side_mode;
    bool s;
    if (mode == 0)      s = ((const unsigned char*)side)[r] != 0;
    else if (mode == 1) s = ((const int*)side)[r] != 0;
    else                s = ((const float*)side)[r] != 0.0f;

    // Write clipped o0 = [us(256), them(256)], us = s ? white : black
    float4* o = (float4*)(g_o0 + (size_t)r * 512);
    float us[8], th[8];
    #pragma unroll
    for (int j = 0; j < 8; j++) {
        us[j] = s ? aw[j] : ab[j];
        th[j] = s ? ab[j] : aw[j];
    }
    #pragma unroll
    for (int j = 0; j < 8; j++) {
        us[j] = fminf(fmaxf(us[j], 0.0f), 1.0f);
        th[j] = fminf(fmaxf(th[j], 0.0f), 1.0f);
    }
    o[lane]      = make_float4(us[0], us[1], us[2], us[3]);
    o[32 + lane] = make_float4(us[4], us[5], us[6], us[7]);
    o[64 + lane] = make_float4(th[0], th[1], th[2], th[3]);
    o[96 + lane] = make_float4(th[4], th[5], th[6], th[7]);
}

// ---------------------------------------------------------------------------
// Tail kernel: l1 -> l2 -> l3 -> sigmoid. One warp per row.
// ---------------------------------------------------------------------------
__global__ __launch_bounds__(256, 2) void nnue_tail_kernel(
    const float* __restrict__ l1_b, const float* __restrict__ l2_b,
    const float* __restrict__ l3_w, const float* __restrict__ l3_b,
    float* __restrict__ out)
{
    extern __shared__ float sm[];
    float* l1wt_sh = sm;               // 16384 floats
    float* l2wt_sh = sm + 16384;       // 1024 floats
    float* o0_sh   = sm + 17408;       // 8 * 512 floats

    int tid = threadIdx.x;
    for (int i = tid; i < 16384; i += 256) l1wt_sh[i] = g_l1wt[i];
    for (int i = tid; i < 1024;  i += 256) l2wt_sh[i] = g_l2wt[i];
    __syncthreads();

    int lane = tid & 31;
    int wrp  = tid >> 5;
    int r = blockIdx.x * ROWS_PER_BLOCK + wrp;

    // Stage this row's o0 into shared
    float* o = o0_sh + wrp * 512;
    const float4* src = (const float4*)(g_o0 + (size_t)r * 512);
    #pragma unroll
    for (int c = 0; c < 4; c++) {
        float4 v = __ldg(src + c * 32 + lane);
        ((float4*)o)[c * 32 + lane] = v;
    }
    __syncwarp();

    // L1
    float s1 = l1_b[lane];
    #pragma unroll 8
    for (int i = 0; i < 512; i++)
        s1 += o[i] * l1wt_sh[i * 32 + lane];
    float o1 = fminf(fmaxf(s1, 0.0f), 1.0f);

    // L2
    float s2 = l2_b[lane];
    #pragma unroll
    for (int i = 0; i < 32; i++) {
        float v = __shfl_sync(0xffffffffu, o1, i);
        s2 += v * l2wt_sh[i * 32 + lane];
    }
    float o2 = fminf(fmaxf(s2, 0.0f), 1.0f);

    // L3 + sigmoid
    float p = o2 * l3_w[lane];
    #pragma unroll
    for (int off = 16; off; off >>= 1)
        p += __shfl_xor_sync(0xffffffffu, p, off);
    if (lane == 0) {
        float t = (p + l3_b[0]) * 1.5f;   // OUTPUT_SCALE / WDL_SCALE
        out[r] = 1.0f / (1.0f + expf(-t));
    }
}

// ---------------------------------------------------------------------------
extern "C" void kernel_launch(void* const* d_in, const int* in_sizes, int n_in,
                              void* d_out, int out_size) {
    const float* white = (const float*)d_in[0];
    const float* black = (const float*)d_in[1];
    const void*  side  = d_in[2];
    const float* ft_w  = (const float*)d_in[3];
    const float* ft_b  = (const float*)d_in[4];
    const float* l1_w  = (const float*)d_in[5];
    const float* l1_b  = (const float*)d_in[6];
    const float* l2_w  = (const float*)d_in[7];
    const float* l2_b  = (const float*)d_in[8];
    const float* l3_w  = (const float*)d_in[9];
    const float* l3_b  = (const float*)d_in[10];
    float* out = (float*)d_out;

    const int tail_smem = (16384 + 1024 + ROWS_PER_BLOCK * 512) * 4;  // 86016
    cudaFuncSetAttribute(nnue_tail_kernel,
                         cudaFuncAttributeMaxDynamicSharedMemorySize,
                         tail_smem);

    side_mode_kernel<<<1, 256>>>((const unsigned char*)side);
    transpose_ft_kernel<<<dim3(N_IN / 32, H0 / 32), dim3(32, 32)>>>(ft_w);
    prep_small_kernel<<<1, 256>>>(l1_w, l2_w);
    nnue_scan_kernel<<<BATCH / ROWS_PER_BLOCK, 256>>>(white, black, side, ft_b);
    nnue_tail_kernel<<<BATCH / ROWS_PER_BLOCK, 256, tail_smem>>>(
        l1_b, l2_b, l3_w, l3_b, out);
}

// round 3
// speedup vs baseline: 1.9374x; 1.2469x over previous
#include <cuda_runtime.h>
#include <cuda_bf16.h>
#include <cuda_fp16.h>
#include <math.h>

#define N_IN   12288
#define H0     256
#define BATCH  8192
#define ROWS_PER_BLOCK 8
#define TROWS  64            // rows per tail block

// Scratch (static device allocations are allowed)
__device__ __half g_ft_wt_h[N_IN * H0];   // (12288, 256) transposed, fp16
__device__ float  g_o0[BATCH * 512];      // clipped, side-swapped accumulator
__device__ int    g_side_mode;            // 0=uint8, 1=int32, 2=float32

// ---------------------------------------------------------------------------
// Detect storage dtype of boolean 'side' by byte patterns (first 8192 bytes).
// ---------------------------------------------------------------------------
__global__ void side_mode_kernel(const unsigned char* __restrict__ p) {
    __shared__ int c3F, cOdd;
    if (threadIdx.x == 0) { c3F = 0; cOdd = 0; }
    __syncthreads();
    int l3f = 0, lodd = 0;
    for (int i = threadIdx.x; i < 8192; i += blockDim.x) {
        unsigned char b = p[i];
        if ((i & 3) == 3 && b == 0x3F) l3f++;
        if ((i & 3) != 0 && b != 0)    lodd++;
    }
    atomicAdd(&c3F, l3f);
    atomicAdd(&cOdd, lodd);
    __syncthreads();
    if (threadIdx.x == 0)
        g_side_mode = (c3F > 0) ? 2 : ((cOdd > 0) ? 0 : 1);
}

// ---------------------------------------------------------------------------
// Tiled transpose + fp16 convert: ft_w (256, 12288) -> g_ft_wt_h (12288, 256)
// ---------------------------------------------------------------------------
__global__ void transpose_ft_kernel(const float* __restrict__ ft_w) {
    __shared__ float tile[32][33];
    int f = blockIdx.x * 32 + threadIdx.x;
    int h = blockIdx.y * 32 + threadIdx.y;
    tile[threadIdx.y][threadIdx.x] = ft_w[h * N_IN + f];
    __syncthreads();
    int oh = blockIdx.y * 32 + threadIdx.x;
    int of = blockIdx.x * 32 + threadIdx.y;
    g_ft_wt_h[of * H0 + oh] = __float2half_rn(tile[threadIdx.x][threadIdx.y]);
}

// ---------------------------------------------------------------------------
// Sparse gather-accumulate: fp16 columns, fp32 accumulation.
// h mapping: acc[j] <-> h = lane*8 + j
// ---------------------------------------------------------------------------
__device__ __forceinline__ void accum_mask(unsigned mask, int fbase, int lane,
                                           float acc[8]) {
    while (mask) {
        int b = __ffs(mask) - 1;
        mask &= mask - 1;
        int f = fbase + b * 4;
        const uint4* wp = (const uint4*)(g_ft_wt_h + (size_t)f * H0);
        uint4 a = __ldg(wp + lane);                 // 8 halves: h = lane*8..+7
        const __half2* hp = (const __half2*)&a;
        float2 f0 = __half22float2(hp[0]);
        float2 f1 = __half22float2(hp[1]);
        float2 f2 = __half22float2(hp[2]);
        float2 f3 = __half22float2(hp[3]);
        acc[0] += f0.x; acc[1] += f0.y;
        acc[2] += f1.x; acc[3] += f1.y;
        acc[4] += f2.x; acc[5] += f2.y;
        acc[6] += f3.x; acc[7] += f3.y;
    }
}

__device__ __forceinline__ void process_chunk(const float4 v[4], int base,
                                              int lane, float acc[8]) {
    #pragma unroll
    for (int c = 0; c < 4; c++) {
        int cb = base + c * 128;
        // Fast path: features are 0/1, so component-sum != 0 iff any active.
        float s = v[c].x + v[c].y + v[c].z + v[c].w;
        unsigned any = __ballot_sync(0xffffffffu, s != 0.0f);
        if (any) {
            unsigned mx = __ballot_sync(0xffffffffu, v[c].x != 0.0f);
            unsigned my = __ballot_sync(0xffffffffu, v[c].y != 0.0f);
            unsigned mz = __ballot_sync(0xffffffffu, v[c].z != 0.0f);
            unsigned mw = __ballot_sync(0xffffffffu, v[c].w != 0.0f);
            accum_mask(mx, cb + 0, lane, acc);
            accum_mask(my, cb + 1, lane, acc);
            accum_mask(mz, cb + 2, lane, acc);
            accum_mask(mw, cb + 3, lane, acc);
        }
    }
}

// ---------------------------------------------------------------------------
// Scan kernel: one warp per batch row, no shared memory.
// ---------------------------------------------------------------------------
__global__ __launch_bounds__(256, 4) void nnue_scan_kernel(
    const float* __restrict__ white, const float* __restrict__ black,
    const void* __restrict__ side, const float* __restrict__ ft_b)
{
    int tid  = threadIdx.x;
    int lane = tid & 31;
    int wrp  = tid >> 5;
    int r = blockIdx.x * ROWS_PER_BLOCK + wrp;

    // bias: h = lane*8 + j
    float4 b0 = __ldg((const float4*)ft_b + lane * 2);
    float4 b1 = __ldg((const float4*)ft_b + lane * 2 + 1);
    float aw[8] = {b0.x, b0.y, b0.z, b0.w, b1.x, b1.y, b1.z, b1.w};
    float ab[8] = {b0.x, b0.y, b0.z, b0.w, b1.x, b1.y, b1.z, b1.w};

    const float4* wrow = (const float4*)(white + (size_t)r * N_IN);
    const float4* brow = (const float4*)(black + (size_t)r * N_IN);

    for (int base = 0; base < N_IN; base += 512) {
        int q = (base >> 2) + lane;
        float4 wv[4], bv[4];
        #pragma unroll
        for (int c = 0; c < 4; c++) wv[c] = __ldcs(wrow + q + c * 32);
        #pragma unroll
        for (int c = 0; c < 4; c++) bv[c] = __ldcs(brow + q + c * 32);
        process_chunk(wv, base, lane, aw);
        process_chunk(bv, base, lane, ab);
    }

    // side flag (auto-detected dtype)
    int mode = g_side_mode;
    bool s;
    if (mode == 0)      s = ((const unsigned char*)side)[r] != 0;
    else if (mode == 1) s = ((const int*)side)[r] != 0;
    else                s = ((const float*)side)[r] != 0.0f;

    float us[8], th[8];
    #pragma unroll
    for (int j = 0; j < 8; j++) {
        float u = s ? aw[j] : ab[j];
        float t = s ? ab[j] : aw[j];
        us[j] = fminf(fmaxf(u, 0.0f), 1.0f);
        th[j] = fminf(fmaxf(t, 0.0f), 1.0f);
    }
    // o0 layout: [us(256) | them(256)], index h = lane*8 + j
    float4* o = (float4*)(g_o0 + (size_t)r * 512);
    o[lane * 2]          = make_float4(us[0], us[1], us[2], us[3]);
    o[lane * 2 + 1]      = make_float4(us[4], us[5], us[6], us[7]);
    o[64 + lane * 2]     = make_float4(th[0], th[1], th[2], th[3]);
    o[64 + lane * 2 + 1] = make_float4(th[4], th[5], th[6], th[7]);
}

// ---------------------------------------------------------------------------
// Tail kernel: blocked GEMM. 64 rows/block, 128 blocks (single wave).
// smem: o0 (64x512), w1 transposed (512x33 pad), w2 (32x33), o1 (64x32).
// ---------------------------------------------------------------------------
__global__ __launch_bounds__(256, 1) void nnue_tail_kernel(
    const float* __restrict__ l1_w, const float* __restrict__ l1_b,
    const float* __restrict__ l2_w, const float* __restrict__ l2_b,
    const float* __restrict__ l3_w, const float* __restrict__ l3_b,
    float* __restrict__ out)
{
    extern __shared__ float sm[];
    float* o0s = sm;                        // 64*512   = 32768
    float* w1s = sm + 32768;                // 512*33   = 16896
    float* w2s = sm + 32768 + 16896;        // 32*33    = 1056
    float* o1s = sm + 32768 + 16896 + 1056; // 64*32    = 2048

    int tid  = threadIdx.x;
    int row0 = blockIdx.x * TROWS;

    // Stage o0 tile (coalesced float4)
    const float4* src = (const float4*)(g_o0 + (size_t)row0 * 512);
    float4* dst = (float4*)o0s;
    for (int i = tid; i < TROWS * 128; i += 256) dst[i] = __ldg(src + i);

    // w1 transposed: w1s[i*33 + h] = l1_w[h*512 + i]
    for (int idx = tid; idx < 32 * 512; idx += 256) {
        int h = idx >> 9, i = idx & 511;
        w1s[i * 33 + h] = __ldg(l1_w + idx);
    }
    // w2 transposed: w2s[h*33 + h2] = l2_w[h2*32 + h]
    for (int idx = tid; idx < 1024; idx += 256) {
        int h2 = idx >> 5, h = idx & 31;
        w2s[h * 33 + h2] = __ldg(l2_w + idx);
    }
    __syncthreads();

    int h  = tid & 31;   // output unit (L1), then h2 (L2)
    int rg = tid >> 5;   // row group: rows rg*8 .. rg*8+7

    // ---- L1: acc[k] = l1_b[h] + sum_i o0[row][i] * w1[i][h]
    float acc[8];
    float bias1 = l1_b[h];
    #pragma unroll
    for (int k = 0; k < 8; k++) acc[k] = bias1;

    for (int i = 0; i < 512; i += 4) {
        float wa = w1s[(i + 0) * 33 + h];
        float wb = w1s[(i + 1) * 33 + h];
        float wc = w1s[(i + 2) * 33 + h];
        float wd = w1s[(i + 3) * 33 + h];
        #pragma unroll
        for (int k = 0; k < 8; k++) {
            const float4 ov = *(const float4*)(o0s + (rg * 8 + k) * 512 + i);
            acc[k] += ov.x * wa + ov.y * wb + ov.z * wc + ov.w * wd;
        }
    }
    #pragma unroll
    for (int k = 0; k < 8; k++) {
        float o1 = fminf(fmaxf(acc[k], 0.0f), 1.0f);
        o1s[(rg * 8 + k) * 32 + h] = o1;
    }
    __syncthreads();

    // ---- L2: lane index h now means h2
    float acc2[8];
    float bias2 = l2_b[h];
    #pragma unroll
    for (int k = 0; k < 8; k++) acc2[k] = bias2;

    #pragma unroll 4
    for (int hh = 0; hh < 32; hh++) {
        float w = w2s[hh * 33 + h];
        #pragma unroll
        for (int k = 0; k < 8; k++)
            acc2[k] += o1s[(rg * 8 + k) * 32 + hh] * w;
    }

    // ---- L3 + sigmoid
    float lw = l3_w[h];
    float p[8];
    #pragma unroll
    for (int k = 0; k < 8; k++) {
        float o2 = fminf(fmaxf(acc2[k], 0.0f), 1.0f);
        p[k] = o2 * lw;
    }
    #pragma unroll
    for (int off = 16; off; off >>= 1) {
        #pragma unroll
        for (int k = 0; k < 8; k++)
            p[k] += __shfl_xor_sync(0xffffffffu, p[k], off);
    }
    if (h < 8) {
        float t = (p[h] + l3_b[0]) * 1.5f;   // OUTPUT_SCALE / WDL_SCALE
        out[row0 + rg * 8 + h] = 1.0f / (1.0f + expf(-t));
    }
}

// ---------------------------------------------------------------------------
extern "C" void kernel_launch(void* const* d_in, const int* in_sizes, int n_in,
                              void* d_out, int out_size) {
    const float* white = (const float*)d_in[0];
    const float* black = (const float*)d_in[1];
    const void*  side  = d_in[2];
    const float* ft_w  = (const float*)d_in[3];
    const float* ft_b  = (const float*)d_in[4];
    const float* l1_w  = (const float*)d_in[5];
    const float* l1_b  = (const float*)d_in[6];
    const float* l2_w  = (const float*)d_in[7];
    const float* l2_b  = (const float*)d_in[8];
    const float* l3_w  = (const float*)d_in[9];
    const float* l3_b  = (const float*)d_in[10];
    float* out = (float*)d_out;

    const int tail_smem = (32768 + 16896 + 1056 + 2048) * 4;  // 211,072 B
    cudaFuncSetAttribute(nnue_tail_kernel,
                         cudaFuncAttributeMaxDynamicSharedMemorySize,
                         tail_smem);

    side_mode_kernel<<<1, 256>>>((const unsigned char*)side);
    transpose_ft_kernel<<<dim3(N_IN / 32, H0 / 32), dim3(32, 32)>>>(ft_w);
    nnue_scan_kernel<<<BATCH / ROWS_PER_BLOCK, 256>>>(white, black, side, ft_b);
    nnue_tail_kernel<<<BATCH / TROWS, 256, tail_smem>>>(
        l1_w, l1_b, l2_w, l2_b, l3_w, l3_b, out);
}